// round 16
// baseline (speedup 1.0000x reference)
#include <cuda_runtime.h>
#include <cuda_fp16.h>
#include <cstdint>

// Problem constants
#define BB   128
#define CIN  2
#define HIDC 150
#define AA   8
#define KIT  30
#define G    49
#define HP   51
#define GG   (G*G)      // 2401
#define HPHP (HP*HP)    // 2601
#define CPAD 160        // padded channel-last stride (halfs)
#define NCH  46         // chunk count padded to even (last = zero chunk)

// ---------------- scratch (device globals; 16B-aligned) ----------------------
__device__ __align__(16) __half g_hT [BB*GG*CPAD];   // conv1 out, channel-last fp16
__device__ __align__(16) __half g_h2T[BB*GG*CPAD];   // conv2 out, channel-last fp16
__device__ __align__(16) uint32_t g_tru[BB*9*4*HPHP];// softmaxed trans, u16 pairs
__device__ __align__(16) float g_rew [BB*HPHP];
__device__ __align__(16) float g_vbuf[2][BB*HPHP];
__device__ __align__(16) __half g_wB2 [NCH*160*32];  // conv2 B [s][n][k32] fp16
__device__ __align__(16) __half g_wBrt[NCH*80*32];   // convrt B [s][n][k32] fp16

// ============================ PTX helpers ====================================
__device__ __forceinline__ uint32_t smem_u32(const void* p) {
    uint32_t a;
    asm("{ .reg .u64 t; cvta.to.shared.u64 t, %1; cvt.u32.u64 %0, t; }" : "=r"(a) : "l"(p));
    return a;
}
__device__ __forceinline__ void cpa16(uint32_t dst, const void* src, uint32_t sz) {
    asm volatile("cp.async.cg.shared.global [%0], [%1], 16, %2;"
                 :: "r"(dst), "l"(src), "r"(sz) : "memory");
}
#define CP_COMMIT() asm volatile("cp.async.commit_group;" ::: "memory")
#define CP_WAIT1()  asm volatile("cp.async.wait_group 1;" ::: "memory")
#define CP_WAIT0()  asm volatile("cp.async.wait_group 0;" ::: "memory")
__device__ __forceinline__ void mma16(float* c, const uint32_t* a, const uint32_t* b) {
    asm volatile("mma.sync.aligned.m16n8k16.row.col.f32.f16.f16.f32 "
        "{%0,%1,%2,%3}, {%4,%5,%6,%7}, {%8,%9}, {%0,%1,%2,%3};"
        : "+f"(c[0]), "+f"(c[1]), "+f"(c[2]), "+f"(c[3])
        : "r"(a[0]), "r"(a[1]), "r"(a[2]), "r"(a[3]), "r"(b[0]), "r"(b[1]));
}
__device__ __forceinline__ void ldsm_x4(uint32_t* r, uint32_t addr) {
    asm volatile("ldmatrix.sync.aligned.m8n8.x4.shared.b16 {%0,%1,%2,%3}, [%4];"
        : "=r"(r[0]), "=r"(r[1]), "=r"(r[2]), "=r"(r[3]) : "r"(addr));
}
__device__ __forceinline__ void ldsm_x2(uint32_t* r, uint32_t addr) {
    asm volatile("ldmatrix.sync.aligned.m8n8.x2.shared.b16 {%0,%1}, [%2];"
        : "=r"(r[0]), "=r"(r[1]) : "r"(addr));
}

// ---------------- weight prep: fp16 B tiles [s][n][k(32)], s<45 real ---------
__global__ void prep_k(const float* __restrict__ h2w,
                       const float* __restrict__ rw,
                       const float* __restrict__ tw) {
    int i = blockIdx.x * blockDim.x + threadIdx.x;
    if (i < NCH*160*32) {
        int k = i & 31, n = (i >> 5) % 160, s = i / (160*32);
        float v = 0.f;
        if (s < 45) {
            int tap = s/5, ci = (s%5)*32 + k;
            if (n < HIDC && ci < HIDC) v = h2w[(n*HIDC + ci)*9 + tap];
        }
        g_wB2[i] = __float2half_rn(v);
    }
    if (i < NCH*80*32) {
        int k = i & 31, n = (i >> 5) % 80, s = i / (80*32);
        float v = 0.f;
        if (s < 45) {
            int tap = s/5, ci = (s%5)*32 + k;
            if (ci < HIDC) {
                if (n == 0)      v = rw[ci*9 + tap];
                else if (n < 73) v = tw[((n-1)*HIDC + ci)*9 + tap];
            }
        }
        g_wBrt[i] = __float2half_rn(v);
    }
}

// -------- conv1 fused with channel-last transpose: grid -> g_hT (fp16) -------
__global__ void conv1T_k(const float* __restrict__ gin,
                         const float* __restrict__ w,
                         const float* __restrict__ bias) {
    __shared__ float ws[HIDC*CIN*9];
    __shared__ float bs[HIDC];
    __shared__ __align__(16) __half tile[32*176];
    int t = threadIdx.x;
    for (int i = t; i < HIDC*CIN*9; i += 256) ws[i] = w[i];
    for (int i = t; i < HIDC; i += 256) bs[i] = bias[i];
    __syncthreads();
    int pos0 = blockIdx.x * 32, b = blockIdx.y;
    int posi = t & 31, colane = t >> 5;
    int pos = pos0 + posi;
    bool okp = pos < GG;
    int y = okp ? pos / G : 0, x = okp ? pos % G : 0;
    float gv[CIN][9];
    #pragma unroll
    for (int ci = 0; ci < CIN; ci++)
        #pragma unroll
        for (int k = 0; k < 9; k++) {
            int r = y + k/3 - 1, c = x + k%3 - 1;
            gv[ci][k] = (okp && r >= 0 && r < G && c >= 0 && c < G)
                        ? gin[(b*CIN + ci)*GG + r*G + c] : 0.f;
        }
    #pragma unroll
    for (int j = 0; j < 20; j++) {
        int co = colane + 8*j;
        float out = 0.f;
        if (co < HIDC) {
            float acc = bs[co];
            #pragma unroll
            for (int ci = 0; ci < CIN; ci++)
                #pragma unroll
                for (int k = 0; k < 9; k++)
                    acc += gv[ci][k] * ws[(co*CIN + ci)*9 + k];
            out = fmaxf(acc, 0.f);
        }
        tile[posi*176 + co] = __float2half_rn(out);
    }
    __syncthreads();
    #pragma unroll
    for (int j = 0; j < 3; j++) {
        int qi = t + 256*j;
        if (qi < 640) {
            int row = qi / 20, q = qi - row*20;
            if (pos0 + row < GG) {
                *(uint4*)&g_hT[((size_t)(b*GG + pos0 + row))*CPAD + q*8] =
                    *(const uint4*)&tile[row*176 + q*8];
            }
        }
    }
}

// ========= fp16 mma.sync m16n8k16 implicit-GEMM conv, ldmatrix fragments =====
// Slot = 2 consecutive K=32 chunks. Fragments via LDSM (x4/x2).
// MODE 0: conv2 (g_hT -> relu+bias -> g_h2T fp16), NFRAG=10 (N=160)
// MODE 1: convrt (g_h2T -> g_rew + v_init + FUSED softmax -> u16 g_tru), NFRAG=5
template<int NFRAG, int OW, int PADC, int PTOT, int MODE, int MINB>
__global__ void __launch_bounds__(256, MINB) mma_conv_k(const float* __restrict__ bias) {
    constexpr int NOUT_PAD = NFRAG * 16;
    constexpr int RSTR = 20;                        // b32 per row
    constexpr int AW = 128 * RSTR;                  // b32 per A chunk (2560)
    constexpr int BW = NOUT_PAD * RSTR;             // b32 per B chunk
    constexpr int ASLOT = 2*AW, BSLOT = 2*BW;       // slot = chunk pair
    constexpr int BQN = NOUT_PAD * 4;               // quads per B chunk
    constexpr int NPAIR = NFRAG/2;
    constexpr bool ODD = (NFRAG & 1) != 0;
    extern __shared__ __align__(16) uint32_t smu[];
    float* biasS = (float*)(smu + 2*ASLOT + 2*BSLOT);
    const __half* inH = (MODE == 0) ? g_hT : g_h2T;
    const __half* wB  = (MODE == 0) ? g_wB2 : g_wBrt;

    int t = threadIdx.x;
    int b = blockIdx.y, tile0 = blockIdx.x * 128;
    uint32_t smb = smem_u32(smu);

    if (MODE == 0) for (int i = t; i < HIDC; i += 256) biasS[i] = bias[i];

    // A-load invariants: thread covers rows (t>>2) and (t>>2)+64, quad t&3
    const int aq = t & 3;
    int yy[2], xx[2];
    uint32_t dA[2];
    #pragma unroll
    for (int i = 0; i < 2; i++) {
        int row = (t >> 2) + 64*i;
        int pos = tile0 + row;
        yy[i] = pos / OW;
        xx[i] = pos - yy[i]*OW;
        dA[i] = (uint32_t)(row*RSTR*4 + aq*16);
    }
    const __half* inB = inH + (size_t)b*GG*CPAD + aq*8;

    // load one pair of chunks (2p, 2p+1) into slot; single commit
    auto load_pair = [&](int p, int slot) {
        #pragma unroll
        for (int j = 0; j < 2; j++) {
            int s = 2*p + j;
            int tap = s / 5, cc = s - tap*5;
            int dyp = tap/3 - PADC, dxp = tap%3 - PADC, ci0 = cc*32;
            bool real = (s < 45);
            uint32_t Ab = smb + (uint32_t)(slot*ASLOT + j*AW)*4;
            #pragma unroll
            for (int i = 0; i < 2; i++) {
                int ir = yy[i] + dyp, ic = xx[i] + dxp;
                bool ok = real && ((unsigned)ir < G) && ((unsigned)ic < G);
                const __half* src = inB + (size_t)(ok ? (ir*G + ic) : 0)*CPAD + ci0;
                cpa16(Ab + dA[i], src, ok ? 16u : 0u);
            }
            uint32_t Bb = smb + (uint32_t)(2*ASLOT + slot*BSLOT + j*BW)*4;
            const __half* wsrc = wB + (size_t)s*NOUT_PAD*32;
            #pragma unroll
            for (int jj = 0; jj < (BQN + 255)/256; jj++) {
                int qi = t + 256*jj;
                if (qi < BQN) {
                    int n = qi >> 2, q = qi & 3;
                    cpa16(Bb + (uint32_t)(n*RSTR*4 + q*16), wsrc + n*32 + q*8, 16u);
                }
            }
        }
        CP_COMMIT();
    };

    const int lane = t & 31, wid = t >> 5;
    const int gid = lane >> 2, tig = lane & 3;
    const int m0w = (wid >> 1) * 32, n0w = (wid & 1) * NFRAG * 8;

    // ldmatrix per-thread byte offsets (invariant; add buffer base at use)
    uint32_t aoff[2][2];
    #pragma unroll
    for (int mf = 0; mf < 2; mf++)
        #pragma unroll
        for (int ks = 0; ks < 2; ks++)
            aoff[mf][ks] = (uint32_t)(((m0w + mf*16 + (lane & 15))*RSTR
                                       + ks*8 + (lane >> 4)*4) * 4);
    uint32_t boff[(NPAIR > 0 ? NPAIR : 1)][2];
    #pragma unroll
    for (int pr = 0; pr < NPAIR; pr++)
        #pragma unroll
        for (int ks = 0; ks < 2; ks++)
            boff[pr][ks] = (uint32_t)(((n0w + pr*16 + ((lane >> 4) << 3) + (lane & 7))*RSTR
                                       + ks*8 + (((lane >> 3) & 1) << 2)) * 4);
    uint32_t boff2[2];
    #pragma unroll
    for (int ks = 0; ks < 2; ks++)
        boff2[ks] = (uint32_t)(((n0w + (NFRAG-1)*8 + (lane & 7))*RSTR
                                + ks*8 + ((((lane & 15) >> 3) & 1) << 2)) * 4);

    float c[2][NFRAG][4];
    #pragma unroll
    for (int mf = 0; mf < 2; mf++)
        #pragma unroll
        for (int nf = 0; nf < NFRAG; nf++)
            #pragma unroll
            for (int e = 0; e < 4; e++) c[mf][nf][e] = 0.f;

    constexpr int NP = NCH/2;     // 23 pairs
    load_pair(0, 0);
    for (int p = 0; p < NP; p++) {
        int cur = p & 1;
        if (p < NP-1) { load_pair(p + 1, cur ^ 1); CP_WAIT1(); }
        else          { CP_WAIT0(); }
        __syncthreads();
        #pragma unroll
        for (int j = 0; j < 2; j++) {
            uint32_t Abase = smb + (uint32_t)(cur*ASLOT + j*AW)*4;
            uint32_t Bbase = smb + (uint32_t)(2*ASLOT + cur*BSLOT + j*BW)*4;
            #pragma unroll
            for (int ks = 0; ks < 2; ks++) {
                uint32_t a[2][4];
                ldsm_x4(a[0], Abase + aoff[0][ks]);
                ldsm_x4(a[1], Abase + aoff[1][ks]);
                uint32_t bv[NFRAG][2];
                #pragma unroll
                for (int pr = 0; pr < NPAIR; pr++) {
                    uint32_t r4[4];
                    ldsm_x4(r4, Bbase + boff[pr][ks]);
                    bv[2*pr][0] = r4[0]; bv[2*pr][1] = r4[1];
                    bv[2*pr+1][0] = r4[2]; bv[2*pr+1][1] = r4[3];
                }
                if (ODD) ldsm_x2(bv[NFRAG-1], Bbase + boff2[ks]);
                #pragma unroll
                for (int nf = 0; nf < NFRAG; nf++) {
                    mma16(c[0][nf], a[0], bv[nf]);
                    mma16(c[1][nf], a[1], bv[nf]);
                }
            }
        }
        __syncthreads();
    }

    // ---- epilogue ----
    if (MODE == 0) {
        #pragma unroll
        for (int mf = 0; mf < 2; mf++) {
            #pragma unroll
            for (int rr = 0; rr < 2; rr++) {
                int pos = tile0 + m0w + mf*16 + gid + rr*8;
                if (pos >= PTOT) continue;
                __half* op = &g_h2T[((size_t)(b*GG + pos))*CPAD];
                #pragma unroll
                for (int nf = 0; nf < NFRAG; nf++) {
                    int co = n0w + nf*8 + 2*tig;
                    float v0 = c[mf][nf][rr*2 + 0], v1 = c[mf][nf][rr*2 + 1];
                    float o0 = (co   < HIDC) ? fmaxf(v0 + biasS[co],   0.f) : 0.f;
                    float o1 = (co+1 < HIDC) ? fmaxf(v1 + biasS[co+1], 0.f) : 0.f;
                    *(__half2*)&op[co] = __floats2half2_rn(o0, o1);
                }
            }
        }
    } else {
        // ---- fused softmax epilogue: regs -> smem qbuf -> u16 g_tru ----
        // Also writes v_init = reward (VI iteration 0 collapses to v = reward).
        float* qbuf = (float*)smu;                 // 128 x 80 fp32 = 40 KB
        #pragma unroll
        for (int mf = 0; mf < 2; mf++) {
            #pragma unroll
            for (int rr = 0; rr < 2; rr++) {
                int m = m0w + mf*16 + gid + rr*8;  // local row 0..127
                #pragma unroll
                for (int nf = 0; nf < NFRAG; nf++) {
                    int co = n0w + nf*8 + 2*tig;
                    float2 v = make_float2(c[mf][nf][rr*2 + 0], c[mf][nf][rr*2 + 1]);
                    *(float2*)&qbuf[m*80 + co] = v;
                }
            }
        }
        __syncthreads();
        // 512 tasks: (pos_l 0..127) x (a2 0..3)
        #pragma unroll
        for (int task = t; task < 512; task += 256) {
            int pos_l = task & 127, a2 = task >> 7;
            int pos = tile0 + pos_l;
            if (pos >= HPHP) continue;
            const float* qr = &qbuf[pos_l*80];
            if (a2 == 0) {
                float r = qr[0];
                g_rew[b*HPHP + pos] = r;
                g_vbuf[0][b*HPHP + pos] = r;       // v after VI step 0
            }
            float v0[9], v1[9];
            float mx0 = -1e30f, mx1 = -1e30f;
            #pragma unroll
            for (int k = 0; k < 9; k++) {
                v0[k] = qr[1 + 18*a2 + k];     mx0 = fmaxf(mx0, v0[k]);
                v1[k] = qr[1 + 18*a2 + 9 + k]; mx1 = fmaxf(mx1, v1[k]);
            }
            float s0 = 0.f, s1 = 0.f;
            #pragma unroll
            for (int k = 0; k < 9; k++) {
                v0[k] = expf(v0[k] - mx0); s0 += v0[k];
                v1[k] = expf(v1[k] - mx1); s1 += v1[k];
            }
            float i0 = 65536.f / s0, i1 = 65536.f / s1;
            #pragma unroll
            for (int k = 0; k < 9; k++) {
                float y0 = fmaf(v0[k], i0, 8388608.f);
                float y1 = fmaf(v1[k], i1, 8388608.f);
                uint32_t pk = __byte_perm(__float_as_uint(y0), __float_as_uint(y1), 0x5410);
                g_tru[((size_t)(b*9 + k)*4 + a2)*HPHP + pos] = pk;
            }
        }
    }
}

// ---------------- middle VI iterations (u16 trans), it = 1..28 ---------------
__global__ void vi_step_k(int iter) {
    int tid = blockIdx.x * blockDim.x + threadIdx.x;
    if (tid >= BB*HPHP) return;
    int b = tid / HPHP, pos = tid - b*HPHP, y = pos / HP, x = pos - y*HP;
    const float* vin = g_vbuf[(iter & 1) ^ 1];
    float p[9];
    #pragma unroll
    for (int k = 0; k < 9; k++) {
        int r = y + k/3 - 1, c = x + k%3 - 1;
        p[k] = (r >= 0 && r < HP && c >= 0 && c < HP)
               ? vin[b*HPHP + r*HP + c] : 0.f;
    }
    float r0 = g_rew[tid];
    float vmax = -1e30f;
    const uint32_t* trb = g_tru + (size_t)b*36*HPHP + pos;
    #pragma unroll
    for (int a2 = 0; a2 < 4; a2++) {
        float q0 = r0, q1 = r0;
        #pragma unroll
        for (int k = 0; k < 9; k++) {
            uint32_t w = trb[(size_t)(k*4 + a2)*HPHP];
            float f0 = __uint_as_float(__byte_perm(w, 0x4B000000u, 0x7410));
            float f1 = __uint_as_float(__byte_perm(w, 0x4B000000u, 0x7432));
            float P0 = fmaf(f0, 1.f/65536.f, -128.f);
            float P1 = fmaf(f1, 1.f/65536.f, -128.f);
            q0 = fmaf(P0, p[k], q0);
            q1 = fmaf(P1, p[k], q1);
        }
        vmax = fmaxf(fmaxf(q0, q1), vmax);
    }
    g_vbuf[iter & 1][tid] = vmax;
}

// -------- last VI iteration fused with head MLP (q kept in registers) --------
__global__ void vi_head_k(int iter,
                          const float* __restrict__ a1w, const float* __restrict__ a1b,
                          const float* __restrict__ a2w, const float* __restrict__ a2b,
                          float* __restrict__ out) {
    __shared__ float a1s[HIDC*AA];
    __shared__ float a2s[AA*HIDC];
    __shared__ float b1s[HIDC];
    __shared__ float b2s[AA];
    int t = threadIdx.x;
    for (int i = t; i < HIDC*AA; i += 256) { a1s[i] = a1w[i]; a2s[i] = a2w[i]; }
    for (int i = t; i < HIDC; i += 256) b1s[i] = a1b[i];
    if (t < AA) b2s[t] = a2b[t];
    __syncthreads();

    int tid = blockIdx.x * blockDim.x + t;
    if (tid >= BB*HPHP) return;
    int b = tid / HPHP, pos = tid - b*HPHP, y = pos / HP, x = pos - y*HP;
    if (y >= G || x >= G) return;       // head consumes only the 49x49 region
    const float* vin = g_vbuf[(iter & 1) ^ 1];
    float p[9];
    #pragma unroll
    for (int k = 0; k < 9; k++) {
        int r = y + k/3 - 1, c = x + k%3 - 1;
        p[k] = (r >= 0 && r < HP && c >= 0 && c < HP)
               ? vin[b*HPHP + r*HP + c] : 0.f;
    }
    float r0 = g_rew[tid];
    float qv[AA];
    const uint32_t* trb = g_tru + (size_t)b*36*HPHP + pos;
    #pragma unroll
    for (int a2 = 0; a2 < 4; a2++) {
        float q0 = r0, q1 = r0;
        #pragma unroll
        for (int k = 0; k < 9; k++) {
            uint32_t w = trb[(size_t)(k*4 + a2)*HPHP];
            float f0 = __uint_as_float(__byte_perm(w, 0x4B000000u, 0x7410));
            float f1 = __uint_as_float(__byte_perm(w, 0x4B000000u, 0x7432));
            float P0 = fmaf(f0, 1.f/65536.f, -128.f);
            float P1 = fmaf(f1, 1.f/65536.f, -128.f);
            q0 = fmaf(P0, p[k], q0);
            q1 = fmaf(P1, p[k], q1);
        }
        qv[2*a2] = q0;
        qv[2*a2 + 1] = q1;
    }
    // head MLP: q[8] -> 150 -> 8
    float lg[AA];
    #pragma unroll
    for (int a = 0; a < AA; a++) lg[a] = 0.f;
    for (int c = 0; c < HIDC; c++) {
        float m = b1s[c];
        #pragma unroll
        for (int a = 0; a < AA; a++) m = fmaf(qv[a], a1s[c*AA + a], m);
        m = fmaxf(m, 0.f);
        #pragma unroll
        for (int a = 0; a < AA; a++) lg[a] = fmaf(m, a2s[a*HIDC + c], lg[a]);
    }
    int opos = y*G + x;
    #pragma unroll
    for (int a = 0; a < AA; a++) out[(b*AA + a)*GG + opos] = lg[a] + b2s[a];
}

// ---------------- launch -----------------------------------------------------
extern "C" void kernel_launch(void* const* d_in, const int* in_sizes, int n_in,
                              void* d_out, int out_size) {
    const float* grid = (const float*)d_in[0];
    const float* h1w = (const float*)d_in[3];
    const float* h1b = (const float*)d_in[4];
    const float* h2w = (const float*)d_in[5];
    const float* h2b = (const float*)d_in[6];
    const float* rw  = (const float*)d_in[7];
    const float* tw  = (const float*)d_in[8];
    const float* a1w = (const float*)d_in[9];
    const float* a1b = (const float*)d_in[10];
    const float* a2w = (const float*)d_in[11];
    const float* a2b = (const float*)d_in[12];
    float* out = (float*)d_out;

    const int SMEM2  = (4*128*20 + 4*160*20) * 4 + HIDC*4 + 64;  // ~94.4 KB
    const int SMEMRT = (4*128*20 + 4*80*20) * 4 + 64;            // ~66.6 KB (>= 40KB qbuf)
    cudaFuncSetAttribute(mma_conv_k<10, G, 1, GG, 0, 2>,
                         cudaFuncAttributeMaxDynamicSharedMemorySize, SMEM2);
    cudaFuncSetAttribute(mma_conv_k<5, HP, 2, HPHP, 1, 3>,
                         cudaFuncAttributeMaxDynamicSharedMemorySize, SMEMRT);

    prep_k<<<(NCH*160*32 + 255)/256, 256>>>(h2w, rw, tw);
    conv1T_k<<<dim3((GG + 31)/32, BB), 256>>>(grid, h1w, h1b);
    mma_conv_k<10, G, 1, GG, 0, 2><<<dim3((GG + 127)/128, BB), 256, SMEM2>>>(h2b);
    mma_conv_k<5, HP, 2, HPHP, 1, 3><<<dim3((HPHP + 127)/128, BB), 256, SMEMRT>>>(nullptr);
    // VI iterations 1..28 (iteration 0 folded into convrt epilogue: v = reward)
    for (int it = 1; it < KIT - 1; it++)
        vi_step_k<<<(BB*HPHP + 255)/256, 256>>>(it);
    // last iteration fused with head
    vi_head_k<<<(BB*HPHP + 255)/256, 256>>>(KIT - 1, a1w, a1b, a2w, a2b, out);
}

// round 17
// speedup vs baseline: 1.5605x; 1.5605x over previous
#include <cuda_runtime.h>
#include <cuda_fp16.h>
#include <cstdint>

// Problem constants
#define BB   128
#define CIN  2
#define HIDC 150
#define AA   8
#define KIT  30
#define G    49
#define HP   51
#define GG   (G*G)      // 2401
#define HPHP (HP*HP)    // 2601
#define CPAD 160        // padded channel-last stride (halfs)
#define NCH  46         // chunk count padded to even (last = zero chunk)

// ---------------- scratch (device globals; 16B-aligned) ----------------------
__device__ __align__(16) __half g_hT [BB*GG*CPAD];   // conv1 out, channel-last fp16
__device__ __align__(16) __half g_h2T[BB*GG*CPAD];   // conv2 out, channel-last fp16
__device__ __align__(16) uint32_t g_tru[BB*9*4*HPHP];// softmaxed trans, u16 pairs
__device__ __align__(16) float g_rew [BB*HPHP];
__device__ __align__(16) float g_vbuf[2][BB*HPHP];
__device__ __align__(16) __half g_wB2 [NCH*160*32];  // conv2 B [s][n][k32] fp16
__device__ __align__(16) __half g_wBrt[NCH*80*32];   // convrt B [s][n][k32] fp16

// ============================ PTX helpers ====================================
__device__ __forceinline__ uint32_t smem_u32(const void* p) {
    uint32_t a;
    asm("{ .reg .u64 t; cvta.to.shared.u64 t, %1; cvt.u32.u64 %0, t; }" : "=r"(a) : "l"(p));
    return a;
}
__device__ __forceinline__ void cpa16(uint32_t dst, const void* src, uint32_t sz) {
    asm volatile("cp.async.cg.shared.global [%0], [%1], 16, %2;"
                 :: "r"(dst), "l"(src), "r"(sz) : "memory");
}
#define CP_COMMIT() asm volatile("cp.async.commit_group;" ::: "memory")
#define CP_WAIT1()  asm volatile("cp.async.wait_group 1;" ::: "memory")
#define CP_WAIT0()  asm volatile("cp.async.wait_group 0;" ::: "memory")
__device__ __forceinline__ void mma16(float* c, const uint32_t* a, const uint32_t* b) {
    asm volatile("mma.sync.aligned.m16n8k16.row.col.f32.f16.f16.f32 "
        "{%0,%1,%2,%3}, {%4,%5,%6,%7}, {%8,%9}, {%0,%1,%2,%3};"
        : "+f"(c[0]), "+f"(c[1]), "+f"(c[2]), "+f"(c[3])
        : "r"(a[0]), "r"(a[1]), "r"(a[2]), "r"(a[3]), "r"(b[0]), "r"(b[1]));
}
__device__ __forceinline__ void ldsm_x4(uint32_t* r, uint32_t addr) {
    asm volatile("ldmatrix.sync.aligned.m8n8.x4.shared.b16 {%0,%1,%2,%3}, [%4];"
        : "=r"(r[0]), "=r"(r[1]), "=r"(r[2]), "=r"(r[3]) : "r"(addr));
}
__device__ __forceinline__ void ldsm_x2(uint32_t* r, uint32_t addr) {
    asm volatile("ldmatrix.sync.aligned.m8n8.x2.shared.b16 {%0,%1}, [%2];"
        : "=r"(r[0]), "=r"(r[1]) : "r"(addr));
}

// ---------------- weight prep: fp16 B tiles [s][n][k(32)], s<45 real ---------
__global__ void prep_k(const float* __restrict__ h2w,
                       const float* __restrict__ rw,
                       const float* __restrict__ tw) {
    int i = blockIdx.x * blockDim.x + threadIdx.x;
    if (i < NCH*160*32) {
        int k = i & 31, n = (i >> 5) % 160, s = i / (160*32);
        float v = 0.f;
        if (s < 45) {
            int tap = s/5, ci = (s%5)*32 + k;
            if (n < HIDC && ci < HIDC) v = h2w[(n*HIDC + ci)*9 + tap];
        }
        g_wB2[i] = __float2half_rn(v);
    }
    if (i < NCH*80*32) {
        int k = i & 31, n = (i >> 5) % 80, s = i / (80*32);
        float v = 0.f;
        if (s < 45) {
            int tap = s/5, ci = (s%5)*32 + k;
            if (ci < HIDC) {
                if (n == 0)      v = rw[ci*9 + tap];
                else if (n < 73) v = tw[((n-1)*HIDC + ci)*9 + tap];
            }
        }
        g_wBrt[i] = __float2half_rn(v);
    }
}

// -------- conv1 fused with channel-last transpose: grid -> g_hT (fp16) -------
__global__ void conv1T_k(const float* __restrict__ gin,
                         const float* __restrict__ w,
                         const float* __restrict__ bias) {
    __shared__ float ws[HIDC*CIN*9];
    __shared__ float bs[HIDC];
    __shared__ __align__(16) __half tile[32*176];
    int t = threadIdx.x;
    for (int i = t; i < HIDC*CIN*9; i += 256) ws[i] = w[i];
    for (int i = t; i < HIDC; i += 256) bs[i] = bias[i];
    __syncthreads();
    int pos0 = blockIdx.x * 32, b = blockIdx.y;
    int posi = t & 31, colane = t >> 5;
    int pos = pos0 + posi;
    bool okp = pos < GG;
    int y = okp ? pos / G : 0, x = okp ? pos % G : 0;
    float gv[CIN][9];
    #pragma unroll
    for (int ci = 0; ci < CIN; ci++)
        #pragma unroll
        for (int k = 0; k < 9; k++) {
            int r = y + k/3 - 1, c = x + k%3 - 1;
            gv[ci][k] = (okp && r >= 0 && r < G && c >= 0 && c < G)
                        ? gin[(b*CIN + ci)*GG + r*G + c] : 0.f;
        }
    #pragma unroll
    for (int j = 0; j < 20; j++) {
        int co = colane + 8*j;
        float out = 0.f;
        if (co < HIDC) {
            float acc = bs[co];
            #pragma unroll
            for (int ci = 0; ci < CIN; ci++)
                #pragma unroll
                for (int k = 0; k < 9; k++)
                    acc += gv[ci][k] * ws[(co*CIN + ci)*9 + k];
            out = fmaxf(acc, 0.f);
        }
        tile[posi*176 + co] = __float2half_rn(out);
    }
    __syncthreads();
    #pragma unroll
    for (int j = 0; j < 3; j++) {
        int qi = t + 256*j;
        if (qi < 640) {
            int row = qi / 20, q = qi - row*20;
            if (pos0 + row < GG) {
                *(uint4*)&g_hT[((size_t)(b*GG + pos0 + row))*CPAD + q*8] =
                    *(const uint4*)&tile[row*176 + q*8];
            }
        }
    }
}

// ========= fp16 mma.sync m16n8k16 implicit-GEMM conv, ldmatrix fragments =====
// MODE 0: conv2 (g_hT -> relu+bias -> g_h2T fp16), NFRAG=10 (N=160)
// MODE 1: convrt (g_h2T -> g_rew + v_init + FUSED softmax -> u16 g_tru), NFRAG=5
template<int NFRAG, int OW, int PADC, int PTOT, int MODE, int MINB>
__global__ void __launch_bounds__(256, MINB) mma_conv_k(const float* __restrict__ bias) {
    constexpr int NOUT_PAD = NFRAG * 16;
    constexpr int RSTR = 20;                        // b32 per row
    constexpr int AW = 128 * RSTR;                  // b32 per A chunk (2560)
    constexpr int BW = NOUT_PAD * RSTR;             // b32 per B chunk
    constexpr int ASLOT = 2*AW, BSLOT = 2*BW;       // slot = chunk pair
    constexpr int BQN = NOUT_PAD * 4;               // quads per B chunk
    constexpr int NPAIR = NFRAG/2;
    constexpr bool ODD = (NFRAG & 1) != 0;
    extern __shared__ __align__(16) uint32_t smu[];
    float* biasS = (float*)(smu + 2*ASLOT + 2*BSLOT);
    const __half* inH = (MODE == 0) ? g_hT : g_h2T;
    const __half* wB  = (MODE == 0) ? g_wB2 : g_wBrt;

    int t = threadIdx.x;
    int b = blockIdx.y, tile0 = blockIdx.x * 128;
    uint32_t smb = smem_u32(smu);

    if (MODE == 0) for (int i = t; i < HIDC; i += 256) biasS[i] = bias[i];

    const int aq = t & 3;
    int yy[2], xx[2];
    uint32_t dA[2];
    #pragma unroll
    for (int i = 0; i < 2; i++) {
        int row = (t >> 2) + 64*i;
        int pos = tile0 + row;
        yy[i] = pos / OW;
        xx[i] = pos - yy[i]*OW;
        dA[i] = (uint32_t)(row*RSTR*4 + aq*16);
    }
    const __half* inB = inH + (size_t)b*GG*CPAD + aq*8;

    auto load_pair = [&](int p, int slot) {
        #pragma unroll
        for (int j = 0; j < 2; j++) {
            int s = 2*p + j;
            int tap = s / 5, cc = s - tap*5;
            int dyp = tap/3 - PADC, dxp = tap%3 - PADC, ci0 = cc*32;
            bool real = (s < 45);
            uint32_t Ab = smb + (uint32_t)(slot*ASLOT + j*AW)*4;
            #pragma unroll
            for (int i = 0; i < 2; i++) {
                int ir = yy[i] + dyp, ic = xx[i] + dxp;
                bool ok = real && ((unsigned)ir < G) && ((unsigned)ic < G);
                const __half* src = inB + (size_t)(ok ? (ir*G + ic) : 0)*CPAD + ci0;
                cpa16(Ab + dA[i], src, ok ? 16u : 0u);
            }
            uint32_t Bb = smb + (uint32_t)(2*ASLOT + slot*BSLOT + j*BW)*4;
            const __half* wsrc = wB + (size_t)s*NOUT_PAD*32;
            #pragma unroll
            for (int jj = 0; jj < (BQN + 255)/256; jj++) {
                int qi = t + 256*jj;
                if (qi < BQN) {
                    int n = qi >> 2, q = qi & 3;
                    cpa16(Bb + (uint32_t)(n*RSTR*4 + q*16), wsrc + n*32 + q*8, 16u);
                }
            }
        }
        CP_COMMIT();
    };

    const int lane = t & 31, wid = t >> 5;
    const int gid = lane >> 2, tig = lane & 3;
    const int m0w = (wid >> 1) * 32, n0w = (wid & 1) * NFRAG * 8;

    uint32_t aoff[2][2];
    #pragma unroll
    for (int mf = 0; mf < 2; mf++)
        #pragma unroll
        for (int ks = 0; ks < 2; ks++)
            aoff[mf][ks] = (uint32_t)(((m0w + mf*16 + (lane & 15))*RSTR
                                       + ks*8 + (lane >> 4)*4) * 4);
    uint32_t boff[(NPAIR > 0 ? NPAIR : 1)][2];
    #pragma unroll
    for (int pr = 0; pr < NPAIR; pr++)
        #pragma unroll
        for (int ks = 0; ks < 2; ks++)
            boff[pr][ks] = (uint32_t)(((n0w + pr*16 + ((lane >> 4) << 3) + (lane & 7))*RSTR
                                       + ks*8 + (((lane >> 3) & 1) << 2)) * 4);
    uint32_t boff2[2];
    #pragma unroll
    for (int ks = 0; ks < 2; ks++)
        boff2[ks] = (uint32_t)(((n0w + (NFRAG-1)*8 + (lane & 7))*RSTR
                                + ks*8 + ((((lane & 15) >> 3) & 1) << 2)) * 4);

    float c[2][NFRAG][4];
    #pragma unroll
    for (int mf = 0; mf < 2; mf++)
        #pragma unroll
        for (int nf = 0; nf < NFRAG; nf++)
            #pragma unroll
            for (int e = 0; e < 4; e++) c[mf][nf][e] = 0.f;

    constexpr int NP = NCH/2;     // 23 pairs
    load_pair(0, 0);
    for (int p = 0; p < NP; p++) {
        int cur = p & 1;
        if (p < NP-1) { load_pair(p + 1, cur ^ 1); CP_WAIT1(); }
        else          { CP_WAIT0(); }
        __syncthreads();
        #pragma unroll
        for (int j = 0; j < 2; j++) {
            uint32_t Abase = smb + (uint32_t)(cur*ASLOT + j*AW)*4;
            uint32_t Bbase = smb + (uint32_t)(2*ASLOT + cur*BSLOT + j*BW)*4;
            #pragma unroll
            for (int ks = 0; ks < 2; ks++) {
                uint32_t a[2][4];
                ldsm_x4(a[0], Abase + aoff[0][ks]);
                ldsm_x4(a[1], Abase + aoff[1][ks]);
                uint32_t bv[NFRAG][2];
                #pragma unroll
                for (int pr = 0; pr < NPAIR; pr++) {
                    uint32_t r4[4];
                    ldsm_x4(r4, Bbase + boff[pr][ks]);
                    bv[2*pr][0] = r4[0]; bv[2*pr][1] = r4[1];
                    bv[2*pr+1][0] = r4[2]; bv[2*pr+1][1] = r4[3];
                }
                if (ODD) ldsm_x2(bv[NFRAG-1], Bbase + boff2[ks]);
                #pragma unroll
                for (int nf = 0; nf < NFRAG; nf++) {
                    mma16(c[0][nf], a[0], bv[nf]);
                    mma16(c[1][nf], a[1], bv[nf]);
                }
            }
        }
        __syncthreads();
    }

    // ---- epilogue ----
    if (MODE == 0) {
        #pragma unroll
        for (int mf = 0; mf < 2; mf++) {
            #pragma unroll
            for (int rr = 0; rr < 2; rr++) {
                int pos = tile0 + m0w + mf*16 + gid + rr*8;
                if (pos >= PTOT) continue;
                __half* op = &g_h2T[((size_t)(b*GG + pos))*CPAD];
                #pragma unroll
                for (int nf = 0; nf < NFRAG; nf++) {
                    int co = n0w + nf*8 + 2*tig;
                    float v0 = c[mf][nf][rr*2 + 0], v1 = c[mf][nf][rr*2 + 1];
                    float o0 = (co   < HIDC) ? fmaxf(v0 + biasS[co],   0.f) : 0.f;
                    float o1 = (co+1 < HIDC) ? fmaxf(v1 + biasS[co+1], 0.f) : 0.f;
                    *(__half2*)&op[co] = __floats2half2_rn(o0, o1);
                }
            }
        }
    } else {
        // ---- fused softmax epilogue: regs -> smem qbuf -> u16 g_tru ----
        float* qbuf = (float*)smu;                 // 128 x 80 fp32 = 40 KB
        #pragma unroll
        for (int mf = 0; mf < 2; mf++) {
            #pragma unroll
            for (int rr = 0; rr < 2; rr++) {
                int m = m0w + mf*16 + gid + rr*8;
                #pragma unroll
                for (int nf = 0; nf < NFRAG; nf++) {
                    int co = n0w + nf*8 + 2*tig;
                    float2 v = make_float2(c[mf][nf][rr*2 + 0], c[mf][nf][rr*2 + 1]);
                    *(float2*)&qbuf[m*80 + co] = v;
                }
            }
        }
        __syncthreads();
        #pragma unroll
        for (int task = t; task < 512; task += 256) {
            int pos_l = task & 127, a2 = task >> 7;
            int pos = tile0 + pos_l;
            if (pos >= HPHP) continue;
            const float* qr = &qbuf[pos_l*80];
            if (a2 == 0) {
                float r = qr[0];
                g_rew[b*HPHP + pos] = r;
                g_vbuf[0][b*HPHP + pos] = r;       // v after VI step 0
            }
            float v0[9], v1[9];
            float mx0 = -1e30f, mx1 = -1e30f;
            #pragma unroll
            for (int k = 0; k < 9; k++) {
                v0[k] = qr[1 + 18*a2 + k];     mx0 = fmaxf(mx0, v0[k]);
                v1[k] = qr[1 + 18*a2 + 9 + k]; mx1 = fmaxf(mx1, v1[k]);
            }
            float s0 = 0.f, s1 = 0.f;
            #pragma unroll
            for (int k = 0; k < 9; k++) {
                v0[k] = expf(v0[k] - mx0); s0 += v0[k];
                v1[k] = expf(v1[k] - mx1); s1 += v1[k];
            }
            float i0 = 65536.f / s0, i1 = 65536.f / s1;
            #pragma unroll
            for (int k = 0; k < 9; k++) {
                float y0 = fmaf(v0[k], i0, 8388608.f);
                float y1 = fmaf(v1[k], i1, 8388608.f);
                uint32_t pk = __byte_perm(__float_as_uint(y0), __float_as_uint(y1), 0x5410);
                g_tru[((size_t)(b*9 + k)*4 + a2)*HPHP + pos] = pk;
            }
        }
    }
}

// ---------------- middle VI iterations (u16 trans), it = 1..28 ---------------
__global__ void vi_step_k(int iter) {
    int tid = blockIdx.x * blockDim.x + threadIdx.x;
    if (tid >= BB*HPHP) return;
    int b = tid / HPHP, pos = tid - b*HPHP, y = pos / HP, x = pos - y*HP;
    const float* vin = g_vbuf[(iter & 1) ^ 1];
    float p[9];
    #pragma unroll
    for (int k = 0; k < 9; k++) {
        int r = y + k/3 - 1, c = x + k%3 - 1;
        p[k] = (r >= 0 && r < HP && c >= 0 && c < HP)
               ? vin[b*HPHP + r*HP + c] : 0.f;
    }
    float r0 = g_rew[tid];
    float vmax = -1e30f;
    const uint32_t* trb = g_tru + (size_t)b*36*HPHP + pos;
    #pragma unroll
    for (int a2 = 0; a2 < 4; a2++) {
        float q0 = r0, q1 = r0;
        #pragma unroll
        for (int k = 0; k < 9; k++) {
            uint32_t w = trb[(size_t)(k*4 + a2)*HPHP];
            float f0 = __uint_as_float(__byte_perm(w, 0x4B000000u, 0x7410));
            float f1 = __uint_as_float(__byte_perm(w, 0x4B000000u, 0x7432));
            float P0 = fmaf(f0, 1.f/65536.f, -128.f);
            float P1 = fmaf(f1, 1.f/65536.f, -128.f);
            q0 = fmaf(P0, p[k], q0);
            q1 = fmaf(P1, p[k], q1);
        }
        vmax = fmaxf(fmaxf(q0, q1), vmax);
    }
    g_vbuf[iter & 1][tid] = vmax;
}

// -------- last VI iteration fused with head MLP (q kept in registers) --------
__global__ void vi_head_k(int iter,
                          const float* __restrict__ a1w, const float* __restrict__ a1b,
                          const float* __restrict__ a2w, const float* __restrict__ a2b,
                          float* __restrict__ out) {
    __shared__ float a1s[HIDC*AA];
    __shared__ float a2s[AA*HIDC];
    __shared__ float b1s[HIDC];
    __shared__ float b2s[AA];
    int t = threadIdx.x;
    for (int i = t; i < HIDC*AA; i += 256) { a1s[i] = a1w[i]; a2s[i] = a2w[i]; }
    for (int i = t; i < HIDC; i += 256) b1s[i] = a1b[i];
    if (t < AA) b2s[t] = a2b[t];
    __syncthreads();

    int tid = blockIdx.x * blockDim.x + t;
    if (tid >= BB*HPHP) return;
    int b = tid / HPHP, pos = tid - b*HPHP, y = pos / HP, x = pos - y*HP;
    if (y >= G || x >= G) return;       // head consumes only the 49x49 region
    const float* vin = g_vbuf[(iter & 1) ^ 1];
    float p[9];
    #pragma unroll
    for (int k = 0; k < 9; k++) {
        int r = y + k/3 - 1, c = x + k%3 - 1;
        p[k] = (r >= 0 && r < HP && c >= 0 && c < HP)
               ? vin[b*HPHP + r*HP + c] : 0.f;
    }
    float r0 = g_rew[tid];
    float qv[AA];
    const uint32_t* trb = g_tru + (size_t)b*36*HPHP + pos;
    #pragma unroll
    for (int a2 = 0; a2 < 4; a2++) {
        float q0 = r0, q1 = r0;
        #pragma unroll
        for (int k = 0; k < 9; k++) {
            uint32_t w = trb[(size_t)(k*4 + a2)*HPHP];
            float f0 = __uint_as_float(__byte_perm(w, 0x4B000000u, 0x7410));
            float f1 = __uint_as_float(__byte_perm(w, 0x4B000000u, 0x7432));
            float P0 = fmaf(f0, 1.f/65536.f, -128.f);
            float P1 = fmaf(f1, 1.f/65536.f, -128.f);
            q0 = fmaf(P0, p[k], q0);
            q1 = fmaf(P1, p[k], q1);
        }
        qv[2*a2] = q0;
        qv[2*a2 + 1] = q1;
    }
    float lg[AA];
    #pragma unroll
    for (int a = 0; a < AA; a++) lg[a] = 0.f;
    for (int c = 0; c < HIDC; c++) {
        float m = b1s[c];
        #pragma unroll
        for (int a = 0; a < AA; a++) m = fmaf(qv[a], a1s[c*AA + a], m);
        m = fmaxf(m, 0.f);
        #pragma unroll
        for (int a = 0; a < AA; a++) lg[a] = fmaf(m, a2s[a*HIDC + c], lg[a]);
    }
    int opos = y*G + x;
    #pragma unroll
    for (int a = 0; a < AA; a++) out[(b*AA + a)*GG + opos] = lg[a] + b2s[a];
}

// ---------------- launch -----------------------------------------------------
extern "C" void kernel_launch(void* const* d_in, const int* in_sizes, int n_in,
                              void* d_out, int out_size) {
    const float* grid = (const float*)d_in[0];
    const float* h1w = (const float*)d_in[3];
    const float* h1b = (const float*)d_in[4];
    const float* h2w = (const float*)d_in[5];
    const float* h2b = (const float*)d_in[6];
    const float* rw  = (const float*)d_in[7];
    const float* tw  = (const float*)d_in[8];
    const float* a1w = (const float*)d_in[9];
    const float* a1b = (const float*)d_in[10];
    const float* a2w = (const float*)d_in[11];
    const float* a2b = (const float*)d_in[12];
    float* out = (float*)d_out;

    const int SMEM2  = (4*128*20 + 4*160*20) * 4 + HIDC*4 + 64;  // ~94.4 KB
    const int SMEMRT = (4*128*20 + 4*80*20) * 4 + 64;            // ~66.6 KB (>= 40KB qbuf)
    cudaFuncSetAttribute(mma_conv_k<10, G, 1, GG, 0, 2>,
                         cudaFuncAttributeMaxDynamicSharedMemorySize, SMEM2);
    cudaFuncSetAttribute(mma_conv_k<5, HP, 2, HPHP, 1, 3>,
                         cudaFuncAttributeMaxDynamicSharedMemorySize, SMEMRT);

    prep_k<<<(NCH*160*32 + 255)/256, 256>>>(h2w, rw, tw);
    conv1T_k<<<dim3((GG + 31)/32, BB), 256>>>(grid, h1w, h1b);
    mma_conv_k<10, G, 1, GG, 0, 2><<<dim3((GG + 127)/128, BB), 256, SMEM2>>>(h2b);
    mma_conv_k<5, HP, 2, HPHP, 1, 3><<<dim3((HPHP + 127)/128, BB), 256, SMEMRT>>>(nullptr);
    // VI iterations 1..28 (iteration 0 folded into convrt epilogue: v = reward)
    for (int it = 1; it < KIT - 1; it++)
        vi_step_k<<<(BB*HPHP + 255)/256, 256>>>(it);
    // last iteration fused with head
    vi_head_k<<<(BB*HPHP + 255)/256, 256>>>(KIT - 1, a1w, a1b, a2w, a2b, out);
}